// round 14
// baseline (speedup 1.0000x reference)
#include <cuda_runtime.h>
#include <cuda_fp16.h>
#include <math.h>

#define Nn   50000
#define Ee   800000
#define HD   128
#define PAD  64
#define EPSV 1e-5f

// ---------------- scratch (__device__ globals: allocation-free) ----------------
__device__ float  g_q[(size_t)Nn * 128];
__device__ float  g_s[(size_t)Nn * 128];
__device__ __half g_kv[(size_t)Nn * 256];   // [node][group 0..31][k half4 | v half4]
__device__ __half g_xh[(size_t)Nn * 128];   // fp16 copy of x
__device__ __half g_wh[4 * 128 * 128];      // fp16 Wq,Wk,Wv,Wskip (K-major)
__device__ int    g_cnt[Nn];
__device__ int    g_csr[(size_t)Nn * PAD];
__device__ float  g_sum[HD];
__device__ float  g_sumsq[HD];

// ---------------- zero counters + stats ----------------
__global__ void zero_kernel() {
    int i = blockIdx.x * blockDim.x + threadIdx.x;
    if (i < Nn) g_cnt[i] = 0;
    if (i < HD) { g_sum[i] = 0.f; g_sumsq[i] = 0.f; }
}

// ---------------- prep (fp16 convert x/W) + CSR scatter, merged ----------------
__global__ void prep_kernel(const float* __restrict__ x,
                            const float* __restrict__ Wq, const float* __restrict__ Wk,
                            const float* __restrict__ Wv, const float* __restrict__ Wsk,
                            const int* __restrict__ src, const int* __restrict__ dst) {
    int i = blockIdx.x * blockDim.x + threadIdx.x;
    if (i < Ee) {                            // CSR bucket scatter (latency hidden under BW work)
        int d = dst[i];
        int pos = atomicAdd(&g_cnt[d], 1);
        g_csr[(size_t)d * PAD + pos] = src[i];
    }
    if (i < Nn * 32) {                       // 1.6M quads of x
        float4 v = ((const float4*)x)[i];
        *(__half2*)(g_xh + (size_t)i * 4)     = __floats2half2_rn(v.x, v.y);
        *(__half2*)(g_xh + (size_t)i * 4 + 2) = __floats2half2_rn(v.z, v.w);
    }
    if (i < 4 * 4096) {                      // 4 matrices x 4096 quads
        int m   = i >> 12;
        int idx = i & 4095;
        const float* W = (m == 0) ? Wq : (m == 1) ? Wk : (m == 2) ? Wv : Wsk;
        float4 v = ((const float4*)W)[idx];
        __half* dstp = g_wh + ((size_t)m << 14) + (size_t)idx * 4;
        *(__half2*)dstp       = __floats2half2_rn(v.x, v.y);
        *(__half2*)(dstp + 2) = __floats2half2_rn(v.z, v.w);
    }
}

// ---------------- cp.async helper (zfill when pred false) ----------------
__device__ __forceinline__ void cp16(unsigned dst, const void* src, bool pred) {
    int sz = pred ? 16 : 0;
    asm volatile("cp.async.cg.shared.global [%0], [%1], 16, %2;\n"
                 :: "r"(dst), "l"(src), "r"(sz));
}

// ---------------- fp16 GEMM: A resident, 8 passes (4 matrices x 2 N-halves) ----------------
__global__ __launch_bounds__(256) void gemm_fp16_kernel(
    const float* __restrict__ bq, const float* __restrict__ bk,
    const float* __restrict__ bv, const float* __restrict__ bsk)
{
    __shared__ __half As[128][136];     // 272B stride: 16B-aligned, LDSM conflict-free
    __shared__ __half Bs[3][32][72];    // 144B stride: 16B-aligned, LDSM conflict-free

    const int t    = threadIdx.x;
    const int row0 = blockIdx.x * 128;
    const int lane = t & 31, wid = t >> 5;
    const int lg = lane >> 2, tg = lane & 3;
    const int wm = wid & 3, wn = wid >> 2;   // 4m x 2n

    const unsigned a_lrow  = (unsigned)(lane & 15);
    const unsigned a_lkof  = (unsigned)((lane >> 4) * 8);
    const unsigned b_lkrow = (unsigned)((lane & 7) + ((lane >> 3) & 1) * 8);
    const unsigned b_lnof  = (unsigned)((lane >> 4) * 8);

    const unsigned as_base = (unsigned)__cvta_generic_to_shared(&As[0][0]);
    const unsigned bs_root = (unsigned)__cvta_generic_to_shared(&Bs[0][0][0]);
    const unsigned BS_STAGE = 32u * 72u * 2u;

    // ---- stage As once: 2048 quads, 8 per thread ----
#pragma unroll
    for (int i = 0; i < 8; i++) {
        int id = t + i * 256;
        int r = id >> 4, q = id & 15;
        unsigned d = (unsigned)__cvta_generic_to_shared(&As[r][q * 8]);
        cp16(d, g_xh + (size_t)(row0 + r) * 128 + q * 8, (row0 + r) < Nn);
    }
    asm volatile("cp.async.commit_group;" ::: "memory");

    const int br = t >> 3, bqd = t & 7;
#define PREFB(n)                                                                          \
    {                                                                                     \
        int p_ = (n) >> 2;                                                                \
        const __half* wsrc = g_wh + ((size_t)(p_ >> 1) << 14)                             \
                           + (size_t)(((n) & 3) * 32 + br) * 128 + (p_ & 1) * 64 + bqd * 8; \
        unsigned d_ = bs_root + ((unsigned)((n) % 3)) * BS_STAGE                          \
                    + (unsigned)(br * 72 + bqd * 8) * 2u;                                 \
        cp16(d_, wsrc, true);                                                             \
        asm volatile("cp.async.commit_group;" ::: "memory");                              \
    }

    PREFB(0);

    float c[2][4][4];

    for (int g = 0; g < 32; g++) {
        if (g + 1 < 32) {
            PREFB(g + 1);
            asm volatile("cp.async.wait_group 1;" ::: "memory");
        } else {
            asm volatile("cp.async.wait_group 0;" ::: "memory");
        }
        __syncthreads();                   // publish chunk g (RAW + WAR, 3-stage ring)

        if ((g & 3) == 0) {
#pragma unroll
            for (int mt = 0; mt < 2; mt++)
#pragma unroll
                for (int nt = 0; nt < 4; nt++)
#pragma unroll
                    for (int j = 0; j < 4; j++) c[mt][nt][j] = 0.f;
        }

        const unsigned bs_base = bs_root + ((unsigned)(g % 3)) * BS_STAGE;
        const int kchunk = (g & 3) * 32;

#pragma unroll
        for (int ks = 0; ks < 2; ks++) {
            int k0  = kchunk + ks * 16;
            int bk0 = ks * 16;
            unsigned a[2][4], b[4][2];
#pragma unroll
            for (int mt = 0; mt < 2; mt++) {
                unsigned row = (unsigned)(wm * 32 + mt * 16) + a_lrow;
                unsigned addr = as_base + (row * 136u + (unsigned)k0 + a_lkof) * 2u;
                asm volatile(
                    "ldmatrix.sync.aligned.m8n8.x4.shared.b16 {%0,%1,%2,%3}, [%4];"
                    : "=r"(a[mt][0]), "=r"(a[mt][1]), "=r"(a[mt][2]), "=r"(a[mt][3])
                    : "r"(addr));
            }
#pragma unroll
            for (int p2 = 0; p2 < 2; p2++) {
                unsigned krow = (unsigned)bk0 + b_lkrow;
                unsigned ncol = (unsigned)(wn * 32 + p2 * 16) + b_lnof;
                unsigned addr = bs_base + (krow * 72u + ncol) * 2u;
                asm volatile(
                    "ldmatrix.sync.aligned.m8n8.x4.trans.shared.b16 {%0,%1,%2,%3}, [%4];"
                    : "=r"(b[2 * p2][0]), "=r"(b[2 * p2][1]),
                      "=r"(b[2 * p2 + 1][0]), "=r"(b[2 * p2 + 1][1])
                    : "r"(addr));
            }
#pragma unroll
            for (int mt = 0; mt < 2; mt++)
#pragma unroll
                for (int nt = 0; nt < 4; nt++) {
                    asm volatile(
                        "mma.sync.aligned.m16n8k16.row.col.f32.f16.f16.f32 "
                        "{%0,%1,%2,%3}, {%4,%5,%6,%7}, {%8,%9}, {%0,%1,%2,%3};"
                        : "+f"(c[mt][nt][0]), "+f"(c[mt][nt][1]),
                          "+f"(c[mt][nt][2]), "+f"(c[mt][nt][3])
                        : "r"(a[mt][0]), "r"(a[mt][1]), "r"(a[mt][2]), "r"(a[mt][3]),
                          "r"(b[nt][0]), "r"(b[nt][1]));
                }
        }

        if ((g & 3) == 3) {
            int pass = g >> 2;
            int bx_  = pass >> 1;
            int nh   = pass & 1;
            const float* bias = (bx_ == 0) ? bq : (bx_ == 1) ? bk : (bx_ == 2) ? bv : bsk;
            const bool is_half = (bx_ == 1) || (bx_ == 2);
            const int  sel     = (bx_ == 2) ? 4 : 0;
            float* outp        = (bx_ == 0) ? g_q : g_s;
#pragma unroll
            for (int mt = 0; mt < 2; mt++) {
                int r0b = row0 + wm * 32 + mt * 16 + lg;
#pragma unroll
                for (int nt = 0; nt < 4; nt++) {
                    int col = nh * 64 + wn * 32 + nt * 8 + 2 * tg;
                    float b0 = bias[col], b1 = bias[col + 1];
                    float v00 = c[mt][nt][0] + b0, v01 = c[mt][nt][1] + b1;
                    float v10 = c[mt][nt][2] + b0, v11 = c[mt][nt][3] + b1;
                    if (is_half) {
                        size_t hoff = (size_t)(col >> 2) * 8 + sel + (col & 3);
                        if (r0b < Nn)
                            *(__half2*)(g_kv + (size_t)r0b * 256 + hoff) = __floats2half2_rn(v00, v01);
                        if (r0b + 8 < Nn)
                            *(__half2*)(g_kv + (size_t)(r0b + 8) * 256 + hoff) = __floats2half2_rn(v10, v11);
                    } else {
                        if (r0b < Nn)
                            *(float2*)(outp + (size_t)r0b * 128 + col) = make_float2(v00, v01);
                        if (r0b + 8 < Nn)
                            *(float2*)(outp + (size_t)(r0b + 8) * 128 + col) = make_float2(v10, v11);
                    }
                }
            }
        }
    }
#undef PREFB
}

// ---------------- warp-per-node attention: fp16 dot, 4-edge ILP, block-aggregated stats ----------------
// Per-edge body: one uint4 gather (k half4 | v half4), HMUL2/HFMA2 4-dim dot,
// 4-shfl 16-lane reduce, plain exp (softmax shift-invariance; |logit|<~8), fp32 v accum.
__device__ __forceinline__ void attn_edge(const uint4& rr, const __half2 qh0, const __half2 qh1,
                                          float4& acc, float& den) {
    const __half2* h = (const __half2*)&rr;
    __half2 d2 = __hfma2(qh1, h[1], __hmul2(qh0, h[0]));
    float p = __low2float(d2) + __high2float(d2);
    p += __shfl_xor_sync(0xffffffffu, p, 8);
    p += __shfl_xor_sync(0xffffffffu, p, 4);
    p += __shfl_xor_sync(0xffffffffu, p, 2);
    p += __shfl_xor_sync(0xffffffffu, p, 1);
    float w = __expf(p);
    float2 v0 = __half22float2(h[2]), v1 = __half22float2(h[3]);
    acc.x += w * v0.x;
    acc.y += w * v0.y;
    acc.z += w * v1.x;
    acc.w += w * v1.y;
    den   += w;
}

__global__ __launch_bounds__(256) void attn_kernel(float* __restrict__ out) {
    __shared__ float sh_sum[128];
    __shared__ float sh_sq[128];
    int t = threadIdx.x;
    if (t < 128) { sh_sum[t] = 0.f; sh_sq[t] = 0.f; }
    __syncthreads();

    int node = blockIdx.x * 8 + (t >> 5);
    int lane = t & 31;
    int col  = lane * 4;

    float4 q = *(const float4*)(g_q + (size_t)node * 128 + col);
    // fold 1/sqrt(64) once, pack to half2 for the HFMA2 dot
    __half2 qh0 = __floats2half2_rn(q.x * 0.125f, q.y * 0.125f);
    __half2 qh1 = __floats2half2_rn(q.z * 0.125f, q.w * 0.125f);

    int nE = g_cnt[node];
    const int* cb = g_csr + (size_t)node * PAD;

    float  den0 = 0.f, den1 = 0.f;
    float4 a0 = make_float4(0.f, 0.f, 0.f, 0.f);
    float4 a1 = make_float4(0.f, 0.f, 0.f, 0.f);

    const __half* kvb = g_kv + lane * 8;

    for (int b = 0; b < nE; b += 32) {
        int rem = nE - b; if (rem > 32) rem = 32;
        int li  = lane < rem ? lane : rem - 1;
        int idx = cb[b + li];                // one coalesced load per 32 edges

        int e = 0;
        for (; e + 3 < rem; e += 4) {        // 4-deep gather ILP
            int s0 = __shfl_sync(0xffffffffu, idx, e);
            int s1 = __shfl_sync(0xffffffffu, idx, e + 1);
            int s2 = __shfl_sync(0xffffffffu, idx, e + 2);
            int s3 = __shfl_sync(0xffffffffu, idx, e + 3);
            uint4 r0 = *(const uint4*)(kvb + (size_t)s0 * 256);
            uint4 r1 = *(const uint4*)(kvb + (size_t)s1 * 256);
            uint4 r2 = *(const uint4*)(kvb + (size_t)s2 * 256);
            uint4 r3 = *(const uint4*)(kvb + (size_t)s3 * 256);
            attn_edge(r0, qh0, qh1, a0, den0);
            attn_edge(r1, qh0, qh1, a1, den1);
            attn_edge(r2, qh0, qh1, a0, den0);
            attn_edge(r3, qh0, qh1, a1, den1);
        }
        for (; e < rem; e++) {
            int s0 = __shfl_sync(0xffffffffu, idx, e);
            uint4 r0 = *(const uint4*)(kvb + (size_t)s0 * 256);
            attn_edge(r0, qh0, qh1, a0, den0);
        }
    }

    float den = den0 + den1;
    float4 acc = make_float4(a0.x + a1.x, a0.y + a1.y, a0.z + a1.z, a0.w + a1.w);

    float inv = (nE > 0) ? 1.f / fmaxf(den, 1e-16f) : 0.f;
    float4 sk = *(const float4*)(g_s + (size_t)node * 128 + col);
    float4 r;
    r.x = acc.x * inv + sk.x;
    r.y = acc.y * inv + sk.y;
    r.z = acc.z * inv + sk.z;
    r.w = acc.w * inv + sk.w;
    *(float4*)(out + (size_t)node * HD + col) = r;

    // block-aggregated BN stats: smem atomics, then 128 global atomics/block
    // (6250 updates/address total -> safely under L2 per-address serialization budget)
    atomicAdd(&sh_sum[col    ], r.x);
    atomicAdd(&sh_sum[col + 1], r.y);
    atomicAdd(&sh_sum[col + 2], r.z);
    atomicAdd(&sh_sum[col + 3], r.w);
    atomicAdd(&sh_sq [col    ], r.x * r.x);
    atomicAdd(&sh_sq [col + 1], r.y * r.y);
    atomicAdd(&sh_sq [col + 2], r.z * r.z);
    atomicAdd(&sh_sq [col + 3], r.w * r.w);
    __syncthreads();
    if (t < 128) {
        atomicAdd(&g_sum[t],   sh_sum[t]);
        atomicAdd(&g_sumsq[t], sh_sq[t]);
    }
}

// ---------------- normalize + fast Mish ----------------
// mish(y) = y * n/(n+2), n = u(u+2), u = e^y  (exact identity for tanh(softplus(y)))
__device__ __forceinline__ float mish_fast(float y) {
    float u = __expf(fminf(y, 30.f));        // y>30: ratio == 1.0f exactly -> returns y
    float n = u * (u + 2.f);
    return y * __fdividef(n, n + 2.f);
}

__global__ void bn_mish_kernel(float* __restrict__ out,
                               const float* __restrict__ gamma,
                               const float* __restrict__ beta) {
    __shared__ float s_scale[128], s_shift[128];
    int t = threadIdx.x;
    if (t < 128) {
        const float invN = 1.f / (float)Nn;
        float mean = g_sum[t] * invN;
        float var  = g_sumsq[t] * invN - mean * mean;
        float sc   = gamma[t] * rsqrtf(var + EPSV);
        s_scale[t] = sc;
        s_shift[t] = beta[t] - mean * sc;
    }
    __syncthreads();

    int i = blockIdx.x * blockDim.x + t;
    if (i >= Nn * 32) return;
    int colb = (i & 31) * 4;

    float4 v = ((const float4*)out)[i];
    float4 y;
    y.x = v.x * s_scale[colb    ] + s_shift[colb    ];
    y.y = v.y * s_scale[colb + 1] + s_shift[colb + 1];
    y.z = v.z * s_scale[colb + 2] + s_shift[colb + 2];
    y.w = v.w * s_scale[colb + 3] + s_shift[colb + 3];
    float4 o;
    o.x = mish_fast(y.x);
    o.y = mish_fast(y.y);
    o.z = mish_fast(y.z);
    o.w = mish_fast(y.w);
    ((float4*)out)[i] = o;
}

// ---------------- launch ----------------
extern "C" void kernel_launch(void* const* d_in, const int* in_sizes, int n_in,
                              void* d_out, int out_size) {
    const float* x   = (const float*)d_in[0];
    const int*   ei  = (const int*)d_in[1];
    const float* Wq  = (const float*)d_in[2];
    const float* bq  = (const float*)d_in[3];
    const float* Wk  = (const float*)d_in[4];
    const float* bk  = (const float*)d_in[5];
    const float* Wv  = (const float*)d_in[6];
    const float* bv  = (const float*)d_in[7];
    const float* Wsk = (const float*)d_in[8];
    const float* bsk = (const float*)d_in[9];
    const float* gamma = (const float*)d_in[10];
    const float* beta  = (const float*)d_in[11];
    float* out = (float*)d_out;

    const int* src = ei;        // edge_index[0]
    const int* dst = ei + Ee;   // edge_index[1]

    zero_kernel<<<(Nn + 255) / 256, 256>>>();                                  // 1
    prep_kernel<<<(Nn * 32 + 255) / 256, 256>>>(x, Wq, Wk, Wv, Wsk, src, dst); // 2 (prep + scatter)
    gemm_fp16_kernel<<<(Nn + 127) / 128, 256>>>(bq, bk, bv, bsk);              // 3
    attn_kernel<<<Nn / 8, 256>>>(out);                                         // 4 <- profiled slot
    bn_mish_kernel<<<(Nn * 32 + 255) / 256, 256>>>(out, gamma, beta);          // 5
}

// round 15
// speedup vs baseline: 1.0292x; 1.0292x over previous
#include <cuda_runtime.h>
#include <cuda_fp16.h>
#include <math.h>

#define Nn   50000
#define Ee   800000
#define HD   128
#define PAD  64
#define EPSV 1e-5f

// ---------------- scratch (__device__ globals: allocation-free) ----------------
__device__ float  g_q[(size_t)Nn * 128];
__device__ float  g_s[(size_t)Nn * 128];
__device__ __half g_kv[(size_t)Nn * 256];   // [node][group 0..31][k half4 | v half4]
__device__ __half g_xh[(size_t)Nn * 128];   // fp16 copy of x
__device__ __half g_wh[4 * 128 * 128];      // fp16 Wq,Wk,Wv,Wskip (K-major)
__device__ int    g_cnt[Nn];
__device__ int    g_csr[(size_t)Nn * PAD];
__device__ float  g_sum[HD];
__device__ float  g_sumsq[HD];

// ---------------- zero counters / stats (split so gemm lands in profiled slot 4) ----------------
__global__ void zero_cnt_kernel() {
    int i = blockIdx.x * blockDim.x + threadIdx.x;
    if (i < Nn) g_cnt[i] = 0;
}
__global__ void zero_stats_kernel() {
    int i = threadIdx.x;
    if (i < HD) { g_sum[i] = 0.f; g_sumsq[i] = 0.f; }
}

// ---------------- prep (fp16 convert x/W) + CSR scatter, merged ----------------
__global__ void prep_kernel(const float* __restrict__ x,
                            const float* __restrict__ Wq, const float* __restrict__ Wk,
                            const float* __restrict__ Wv, const float* __restrict__ Wsk,
                            const int* __restrict__ src, const int* __restrict__ dst) {
    int i = blockIdx.x * blockDim.x + threadIdx.x;
    if (i < Ee) {                            // CSR bucket scatter (latency hidden under BW work)
        int d = dst[i];
        int pos = atomicAdd(&g_cnt[d], 1);
        g_csr[(size_t)d * PAD + pos] = src[i];
    }
    if (i < Nn * 32) {                       // 1.6M quads of x
        float4 v = ((const float4*)x)[i];
        *(__half2*)(g_xh + (size_t)i * 4)     = __floats2half2_rn(v.x, v.y);
        *(__half2*)(g_xh + (size_t)i * 4 + 2) = __floats2half2_rn(v.z, v.w);
    }
    if (i < 4 * 4096) {                      // 4 matrices x 4096 quads
        int m   = i >> 12;
        int idx = i & 4095;
        const float* W = (m == 0) ? Wq : (m == 1) ? Wk : (m == 2) ? Wv : Wsk;
        float4 v = ((const float4*)W)[idx];
        __half* dstp = g_wh + ((size_t)m << 14) + (size_t)idx * 4;
        *(__half2*)dstp       = __floats2half2_rn(v.x, v.y);
        *(__half2*)(dstp + 2) = __floats2half2_rn(v.z, v.w);
    }
}

// ---------------- cp.async helper (zfill when pred false) ----------------
__device__ __forceinline__ void cp16(unsigned dst, const void* src, bool pred) {
    int sz = pred ? 16 : 0;
    asm volatile("cp.async.cg.shared.global [%0], [%1], 16, %2;\n"
                 :: "r"(dst), "l"(src), "r"(sz));
}

// ---------------- fp16 GEMM: A resident, 8 passes (4 matrices x 2 N-halves) ----------------
__global__ __launch_bounds__(256) void gemm_fp16_kernel(
    const float* __restrict__ bq, const float* __restrict__ bk,
    const float* __restrict__ bv, const float* __restrict__ bsk)
{
    __shared__ __half As[128][136];     // 272B stride: 16B-aligned, LDSM conflict-free
    __shared__ __half Bs[3][32][72];    // 144B stride: 16B-aligned, LDSM conflict-free

    const int t    = threadIdx.x;
    const int row0 = blockIdx.x * 128;
    const int lane = t & 31, wid = t >> 5;
    const int lg = lane >> 2, tg = lane & 3;
    const int wm = wid & 3, wn = wid >> 2;   // 4m x 2n

    const unsigned a_lrow  = (unsigned)(lane & 15);
    const unsigned a_lkof  = (unsigned)((lane >> 4) * 8);
    const unsigned b_lkrow = (unsigned)((lane & 7) + ((lane >> 3) & 1) * 8);
    const unsigned b_lnof  = (unsigned)((lane >> 4) * 8);

    const unsigned as_base = (unsigned)__cvta_generic_to_shared(&As[0][0]);
    const unsigned bs_root = (unsigned)__cvta_generic_to_shared(&Bs[0][0][0]);
    const unsigned BS_STAGE = 32u * 72u * 2u;

    // ---- stage As once: 2048 quads, 8 per thread ----
#pragma unroll
    for (int i = 0; i < 8; i++) {
        int id = t + i * 256;
        int r = id >> 4, q = id & 15;
        unsigned d = (unsigned)__cvta_generic_to_shared(&As[r][q * 8]);
        cp16(d, g_xh + (size_t)(row0 + r) * 128 + q * 8, (row0 + r) < Nn);
    }
    asm volatile("cp.async.commit_group;" ::: "memory");

    const int br = t >> 3, bqd = t & 7;
#define PREFB(n)                                                                          \
    {                                                                                     \
        int p_ = (n) >> 2;                                                                \
        const __half* wsrc = g_wh + ((size_t)(p_ >> 1) << 14)                             \
                           + (size_t)(((n) & 3) * 32 + br) * 128 + (p_ & 1) * 64 + bqd * 8; \
        unsigned d_ = bs_root + ((unsigned)((n) % 3)) * BS_STAGE                          \
                    + (unsigned)(br * 72 + bqd * 8) * 2u;                                 \
        cp16(d_, wsrc, true);                                                             \
        asm volatile("cp.async.commit_group;" ::: "memory");                              \
    }

    PREFB(0);

    float c[2][4][4];

    for (int g = 0; g < 32; g++) {
        if (g + 1 < 32) {
            PREFB(g + 1);
            asm volatile("cp.async.wait_group 1;" ::: "memory");
        } else {
            asm volatile("cp.async.wait_group 0;" ::: "memory");
        }
        __syncthreads();                   // publish chunk g (RAW + WAR, 3-stage ring)

        if ((g & 3) == 0) {
#pragma unroll
            for (int mt = 0; mt < 2; mt++)
#pragma unroll
                for (int nt = 0; nt < 4; nt++)
#pragma unroll
                    for (int j = 0; j < 4; j++) c[mt][nt][j] = 0.f;
        }

        const unsigned bs_base = bs_root + ((unsigned)(g % 3)) * BS_STAGE;
        const int kchunk = (g & 3) * 32;

#pragma unroll
        for (int ks = 0; ks < 2; ks++) {
            int k0  = kchunk + ks * 16;
            int bk0 = ks * 16;
            unsigned a[2][4], b[4][2];
#pragma unroll
            for (int mt = 0; mt < 2; mt++) {
                unsigned row = (unsigned)(wm * 32 + mt * 16) + a_lrow;
                unsigned addr = as_base + (row * 136u + (unsigned)k0 + a_lkof) * 2u;
                asm volatile(
                    "ldmatrix.sync.aligned.m8n8.x4.shared.b16 {%0,%1,%2,%3}, [%4];"
                    : "=r"(a[mt][0]), "=r"(a[mt][1]), "=r"(a[mt][2]), "=r"(a[mt][3])
                    : "r"(addr));
            }
#pragma unroll
            for (int p2 = 0; p2 < 2; p2++) {
                unsigned krow = (unsigned)bk0 + b_lkrow;
                unsigned ncol = (unsigned)(wn * 32 + p2 * 16) + b_lnof;
                unsigned addr = bs_base + (krow * 72u + ncol) * 2u;
                asm volatile(
                    "ldmatrix.sync.aligned.m8n8.x4.trans.shared.b16 {%0,%1,%2,%3}, [%4];"
                    : "=r"(b[2 * p2][0]), "=r"(b[2 * p2][1]),
                      "=r"(b[2 * p2 + 1][0]), "=r"(b[2 * p2 + 1][1])
                    : "r"(addr));
            }
#pragma unroll
            for (int mt = 0; mt < 2; mt++)
#pragma unroll
                for (int nt = 0; nt < 4; nt++) {
                    asm volatile(
                        "mma.sync.aligned.m16n8k16.row.col.f32.f16.f16.f32 "
                        "{%0,%1,%2,%3}, {%4,%5,%6,%7}, {%8,%9}, {%0,%1,%2,%3};"
                        : "+f"(c[mt][nt][0]), "+f"(c[mt][nt][1]),
                          "+f"(c[mt][nt][2]), "+f"(c[mt][nt][3])
                        : "r"(a[mt][0]), "r"(a[mt][1]), "r"(a[mt][2]), "r"(a[mt][3]),
                          "r"(b[nt][0]), "r"(b[nt][1]));
                }
        }

        if ((g & 3) == 3) {
            int pass = g >> 2;
            int bx_  = pass >> 1;
            int nh   = pass & 1;
            const float* bias = (bx_ == 0) ? bq : (bx_ == 1) ? bk : (bx_ == 2) ? bv : bsk;
            const bool is_half = (bx_ == 1) || (bx_ == 2);
            const int  sel     = (bx_ == 2) ? 4 : 0;
            float* outp        = (bx_ == 0) ? g_q : g_s;
#pragma unroll
            for (int mt = 0; mt < 2; mt++) {
                int r0b = row0 + wm * 32 + mt * 16 + lg;
#pragma unroll
                for (int nt = 0; nt < 4; nt++) {
                    int col = nh * 64 + wn * 32 + nt * 8 + 2 * tg;
                    float b0 = bias[col], b1 = bias[col + 1];
                    float v00 = c[mt][nt][0] + b0, v01 = c[mt][nt][1] + b1;
                    float v10 = c[mt][nt][2] + b0, v11 = c[mt][nt][3] + b1;
                    if (is_half) {
                        size_t hoff = (size_t)(col >> 2) * 8 + sel + (col & 3);
                        if (r0b < Nn)
                            *(__half2*)(g_kv + (size_t)r0b * 256 + hoff) = __floats2half2_rn(v00, v01);
                        if (r0b + 8 < Nn)
                            *(__half2*)(g_kv + (size_t)(r0b + 8) * 256 + hoff) = __floats2half2_rn(v10, v11);
                    } else {
                        if (r0b < Nn)
                            *(float2*)(outp + (size_t)r0b * 128 + col) = make_float2(v00, v01);
                        if (r0b + 8 < Nn)
                            *(float2*)(outp + (size_t)(r0b + 8) * 128 + col) = make_float2(v10, v11);
                    }
                }
            }
        }
    }
#undef PREFB
}

// ---------------- warp-per-node attention: plain-exp softmax, block-aggregated stats ----------------
// (round-13 configuration: 2-edge ILP, fp32 dot, smem-atomic stats = measured 65us)
__global__ __launch_bounds__(256) void attn_kernel(float* __restrict__ out) {
    __shared__ float sh_sum[128];
    __shared__ float sh_sq[128];
    int t = threadIdx.x;
    if (t < 128) { sh_sum[t] = 0.f; sh_sq[t] = 0.f; }
    __syncthreads();

    int node = blockIdx.x * 8 + (t >> 5);
    int lane = t & 31;
    int col  = lane * 4;

    float4 q = *(const float4*)(g_q + (size_t)node * 128 + col);
    q.x *= 0.125f; q.y *= 0.125f; q.z *= 0.125f; q.w *= 0.125f;   // fold 1/sqrt(64)

    int nE = g_cnt[node];
    const int* cb = g_csr + (size_t)node * PAD;

    float  den0 = 0.f, den1 = 0.f;
    float4 a0 = make_float4(0.f, 0.f, 0.f, 0.f);
    float4 a1 = make_float4(0.f, 0.f, 0.f, 0.f);

    for (int b = 0; b < nE; b += 32) {
        int rem = nE - b; if (rem > 32) rem = 32;
        int li  = lane < rem ? lane : rem - 1;
        int idx = cb[b + li];                // one coalesced load per 32 edges

        int e = 0;
        for (; e + 1 < rem; e += 2) {
            int sA = __shfl_sync(0xffffffffu, idx, e);
            int sB = __shfl_sync(0xffffffffu, idx, e + 1);
            uint4 rA = *(const uint4*)(g_kv + (size_t)sA * 256 + lane * 8);
            uint4 rB = *(const uint4*)(g_kv + (size_t)sB * 256 + lane * 8);
            const __half2* hA = (const __half2*)&rA;
            const __half2* hB = (const __half2*)&rB;

            float2 kA0 = __half22float2(hA[0]), kA1 = __half22float2(hA[1]);
            float2 kB0 = __half22float2(hB[0]), kB1 = __half22float2(hB[1]);
            float pA = q.x * kA0.x + q.y * kA0.y + q.z * kA1.x + q.w * kA1.y;
            float pB = q.x * kB0.x + q.y * kB0.y + q.z * kB1.x + q.w * kB1.y;
            pA += __shfl_xor_sync(0xffffffffu, pA, 8);
            pB += __shfl_xor_sync(0xffffffffu, pB, 8);
            pA += __shfl_xor_sync(0xffffffffu, pA, 4);
            pB += __shfl_xor_sync(0xffffffffu, pB, 4);
            pA += __shfl_xor_sync(0xffffffffu, pA, 2);
            pB += __shfl_xor_sync(0xffffffffu, pB, 2);
            pA += __shfl_xor_sync(0xffffffffu, pA, 1);
            pB += __shfl_xor_sync(0xffffffffu, pB, 1);

            float wA = __expf(pA);
            float wB = __expf(pB);

            float2 vA0 = __half22float2(hA[2]), vA1 = __half22float2(hA[3]);
            float2 vB0 = __half22float2(hB[2]), vB1 = __half22float2(hB[3]);
            a0.x += wA * vA0.x;  a1.x += wB * vB0.x;
            a0.y += wA * vA0.y;  a1.y += wB * vB0.y;
            a0.z += wA * vA1.x;  a1.z += wB * vB1.x;
            a0.w += wA * vA1.y;  a1.w += wB * vB1.y;
            den0 += wA;          den1 += wB;
        }
        if (e < rem) {
            int sA = __shfl_sync(0xffffffffu, idx, e);
            uint4 rA = *(const uint4*)(g_kv + (size_t)sA * 256 + lane * 8);
            const __half2* hA = (const __half2*)&rA;
            float2 kA0 = __half22float2(hA[0]), kA1 = __half22float2(hA[1]);
            float pA = q.x * kA0.x + q.y * kA0.y + q.z * kA1.x + q.w * kA1.y;
            pA += __shfl_xor_sync(0xffffffffu, pA, 8);
            pA += __shfl_xor_sync(0xffffffffu, pA, 4);
            pA += __shfl_xor_sync(0xffffffffu, pA, 2);
            pA += __shfl_xor_sync(0xffffffffu, pA, 1);
            float wA = __expf(pA);
            float2 vA0 = __half22float2(hA[2]), vA1 = __half22float2(hA[3]);
            a0.x += wA * vA0.x;
            a0.y += wA * vA0.y;
            a0.z += wA * vA1.x;
            a0.w += wA * vA1.y;
            den0 += wA;
        }
    }

    float den = den0 + den1;
    float4 acc = make_float4(a0.x + a1.x, a0.y + a1.y, a0.z + a1.z, a0.w + a1.w);

    float inv = (nE > 0) ? 1.f / fmaxf(den, 1e-16f) : 0.f;
    float4 sk = *(const float4*)(g_s + (size_t)node * 128 + col);
    float4 r;
    r.x = acc.x * inv + sk.x;
    r.y = acc.y * inv + sk.y;
    r.z = acc.z * inv + sk.z;
    r.w = acc.w * inv + sk.w;
    *(float4*)(out + (size_t)node * HD + col) = r;

    atomicAdd(&sh_sum[col    ], r.x);
    atomicAdd(&sh_sum[col + 1], r.y);
    atomicAdd(&sh_sum[col + 2], r.z);
    atomicAdd(&sh_sum[col + 3], r.w);
    atomicAdd(&sh_sq [col    ], r.x * r.x);
    atomicAdd(&sh_sq [col + 1], r.y * r.y);
    atomicAdd(&sh_sq [col + 2], r.z * r.z);
    atomicAdd(&sh_sq [col + 3], r.w * r.w);
    __syncthreads();
    if (t < 128) {
        atomicAdd(&g_sum[t],   sh_sum[t]);
        atomicAdd(&g_sumsq[t], sh_sq[t]);
    }
}

// ---------------- normalize + fast Mish ----------------
// mish(y) = y * n/(n+2), n = u(u+2), u = e^y  (exact identity for tanh(softplus(y)))
__device__ __forceinline__ float mish_fast(float y) {
    float u = __expf(fminf(y, 30.f));        // y>30: ratio == 1.0f exactly -> returns y
    float n = u * (u + 2.f);
    return y * __fdividef(n, n + 2.f);
}

__global__ void bn_mish_kernel(float* __restrict__ out,
                               const float* __restrict__ gamma,
                               const float* __restrict__ beta) {
    __shared__ float s_scale[128], s_shift[128];
    int t = threadIdx.x;
    if (t < 128) {
        const float invN = 1.f / (float)Nn;
        float mean = g_sum[t] * invN;
        float var  = g_sumsq[t] * invN - mean * mean;
        float sc   = gamma[t] * rsqrtf(var + EPSV);
        s_scale[t] = sc;
        s_shift[t] = beta[t] - mean * sc;
    }
    __syncthreads();

    int i = blockIdx.x * blockDim.x + t;
    if (i >= Nn * 32) return;
    int colb = (i & 31) * 4;

    float4 v = ((const float4*)out)[i];
    float4 y;
    y.x = v.x * s_scale[colb    ] + s_shift[colb    ];
    y.y = v.y * s_scale[colb + 1] + s_shift[colb + 1];
    y.z = v.z * s_scale[colb + 2] + s_shift[colb + 2];
    y.w = v.w * s_scale[colb + 3] + s_shift[colb + 3];
    float4 o;
    o.x = mish_fast(y.x);
    o.y = mish_fast(y.y);
    o.z = mish_fast(y.z);
    o.w = mish_fast(y.w);
    ((float4*)out)[i] = o;
}

// ---------------- launch ----------------
extern "C" void kernel_launch(void* const* d_in, const int* in_sizes, int n_in,
                              void* d_out, int out_size) {
    const float* x   = (const float*)d_in[0];
    const int*   ei  = (const int*)d_in[1];
    const float* Wq  = (const float*)d_in[2];
    const float* bq  = (const float*)d_in[3];
    const float* Wk  = (const float*)d_in[4];
    const float* bk  = (const float*)d_in[5];
    const float* Wv  = (const float*)d_in[6];
    const float* bv  = (const float*)d_in[7];
    const float* Wsk = (const float*)d_in[8];
    const float* bsk = (const float*)d_in[9];
    const float* gamma = (const float*)d_in[10];
    const float* beta  = (const float*)d_in[11];
    float* out = (float*)d_out;

    const int* src = ei;        // edge_index[0]
    const int* dst = ei + Ee;   // edge_index[1]

    zero_cnt_kernel<<<(Nn + 255) / 256, 256>>>();                              // 1
    zero_stats_kernel<<<1, 128>>>();                                           // 2
    prep_kernel<<<(Nn * 32 + 255) / 256, 256>>>(x, Wq, Wk, Wv, Wsk, src, dst); // 3 (prep + scatter)
    gemm_fp16_kernel<<<(Nn + 127) / 128, 256>>>(bq, bk, bv, bsk);              // 4 <- profiled slot
    attn_kernel<<<Nn / 8, 256>>>(out);                                         // 5
    bn_mish_kernel<<<(Nn * 32 + 255) / 256, 256>>>(out, gamma, beta);          // 6
}